// round 10
// baseline (speedup 1.0000x reference)
#include <cuda_runtime.h>

// Problem constants
#define BATCH   2
#define S_LEN   2048
#define EMB     1024
#define NHEAD   16
#define HDIM    64
#define MROWS   (BATCH * S_LEN)          // 4096

// Scratch (allocation-free rule: static __device__ arrays)
__device__ float g_q[BATCH * NHEAD * S_LEN * HDIM];   // [b,h,s,d]
__device__ float g_k[BATCH * NHEAD * S_LEN * HDIM];
__device__ float g_v[BATCH * NHEAD * S_LEN * HDIM];
__device__ float g_att[MROWS * EMB];                  // [b,s,e] e = h*64+d

// ---------------------------------------------------------------------------
// SGEMM: C = A @ B^T, A[M,K] row-major, B[N,K] row-major. 128x128 tile, BK=8,
// 256 threads, 8x8 per thread. v2: register prefetch of the next K-chunk is
// issued right after the first sync, hiding gmem latency behind the FFMA block
// (R1 measured issue=61% with the load latency exposed).
// NOTE: zero inline asm in this file — every asm-bearing variant tripped a
// 128MiB local-memory pool allocation (harness rule violation), root cause
// not yet visible without a passing run's ncu.
// ---------------------------------------------------------------------------
#define BM 128
#define BN 128
#define BKK 8

// MODE 0: QKV projection. blockIdx.z in {0,1,2} selects weight & destination,
//         epilogue scatters into [b,h,s,d] layout.
__global__ __launch_bounds__(256) void qkv_gemm(
    const float* __restrict__ X,
    const float* __restrict__ Wq,
    const float* __restrict__ Wk,
    const float* __restrict__ Wv)
{
    const int K = EMB;
    const float* W   = (blockIdx.z == 0) ? Wq : (blockIdx.z == 1) ? Wk : Wv;
    float*       Dst = (blockIdx.z == 0) ? g_q : (blockIdx.z == 1) ? g_k : g_v;

    __shared__ float As[BKK][BM];
    __shared__ float Bs[BKK][BN];

    const int tid = threadIdx.x;
    const int m0  = blockIdx.y * BM;
    const int n0  = blockIdx.x * BN;

    const int lrow = tid >> 1;          // 0..127
    const int lcol = (tid & 1) * 4;     // 0 or 4

    const float* Aptr = X + (size_t)(m0 + lrow) * K + lcol;
    const float* Bptr = W + (size_t)(n0 + lrow) * K + lcol;

    float acc[8][8];
#pragma unroll
    for (int i = 0; i < 8; i++)
#pragma unroll
        for (int j = 0; j < 8; j++) acc[i][j] = 0.f;

    const int ty = tid >> 4;   // 0..15
    const int tx = tid & 15;   // 0..15

    float4 a_cur = *(const float4*)(Aptr);
    float4 b_cur = *(const float4*)(Bptr);

    for (int k0 = 0; k0 < K; k0 += BKK) {
        As[lcol + 0][lrow] = a_cur.x; As[lcol + 1][lrow] = a_cur.y;
        As[lcol + 2][lrow] = a_cur.z; As[lcol + 3][lrow] = a_cur.w;
        Bs[lcol + 0][lrow] = b_cur.x; Bs[lcol + 1][lrow] = b_cur.y;
        Bs[lcol + 2][lrow] = b_cur.z; Bs[lcol + 3][lrow] = b_cur.w;
        __syncthreads();

        // Prefetch next chunk (overlaps with the FFMA block below).
        if (k0 + BKK < K) {
            a_cur = *(const float4*)(Aptr + k0 + BKK);
            b_cur = *(const float4*)(Bptr + k0 + BKK);
        }

#pragma unroll
        for (int kk = 0; kk < BKK; kk++) {
            float4 a0 = *(const float4*)&As[kk][ty * 8];
            float4 a1 = *(const float4*)&As[kk][ty * 8 + 4];
            float4 b0 = *(const float4*)&Bs[kk][tx * 8];
            float4 b1 = *(const float4*)&Bs[kk][tx * 8 + 4];
            float ar[8] = {a0.x, a0.y, a0.z, a0.w, a1.x, a1.y, a1.z, a1.w};
            float br[8] = {b0.x, b0.y, b0.z, b0.w, b1.x, b1.y, b1.z, b1.w};
#pragma unroll
            for (int i = 0; i < 8; i++)
#pragma unroll
                for (int j = 0; j < 8; j++) acc[i][j] += ar[i] * br[j];
        }
        __syncthreads();
    }

    // Epilogue: scatter into [b,h,s,d]. n-span of 8 never crosses a head
    // boundary (64 % 8 == 0) -> float4 stores are contiguous in d.
#pragma unroll
    for (int i = 0; i < 8; i++) {
        const int m = m0 + ty * 8 + i;
        const int b = m >> 11;          // /2048
        const int s = m & 2047;
#pragma unroll
        for (int j = 0; j < 8; j += 4) {
            const int n = n0 + tx * 8 + j;
            const int h = n >> 6;
            const int d = n & 63;
            float4 v = make_float4(acc[i][j], acc[i][j+1], acc[i][j+2], acc[i][j+3]);
            *(float4*)&Dst[((size_t)(b * NHEAD + h) * S_LEN + s) * HDIM + d] = v;
        }
    }
}

// MODE 1: output projection out = g_att @ Wo^T + bo
__global__ __launch_bounds__(256) void outproj_gemm(
    const float* __restrict__ Wo,
    const float* __restrict__ bo,
    float* __restrict__ Out)
{
    const int K = EMB;
    const float* A = g_att;

    __shared__ float As[BKK][BM];
    __shared__ float Bs[BKK][BN];

    const int tid = threadIdx.x;
    const int m0  = blockIdx.y * BM;
    const int n0  = blockIdx.x * BN;

    const int lrow = tid >> 1;
    const int lcol = (tid & 1) * 4;

    const float* Aptr = A  + (size_t)(m0 + lrow) * K + lcol;
    const float* Bptr = Wo + (size_t)(n0 + lrow) * K + lcol;

    float acc[8][8];
#pragma unroll
    for (int i = 0; i < 8; i++)
#pragma unroll
        for (int j = 0; j < 8; j++) acc[i][j] = 0.f;

    const int ty = tid >> 4;
    const int tx = tid & 15;

    float4 a_cur = *(const float4*)(Aptr);
    float4 b_cur = *(const float4*)(Bptr);

    for (int k0 = 0; k0 < K; k0 += BKK) {
        As[lcol + 0][lrow] = a_cur.x; As[lcol + 1][lrow] = a_cur.y;
        As[lcol + 2][lrow] = a_cur.z; As[lcol + 3][lrow] = a_cur.w;
        Bs[lcol + 0][lrow] = b_cur.x; Bs[lcol + 1][lrow] = b_cur.y;
        Bs[lcol + 2][lrow] = b_cur.z; Bs[lcol + 3][lrow] = b_cur.w;
        __syncthreads();

        if (k0 + BKK < K) {
            a_cur = *(const float4*)(Aptr + k0 + BKK);
            b_cur = *(const float4*)(Bptr + k0 + BKK);
        }

#pragma unroll
        for (int kk = 0; kk < BKK; kk++) {
            float4 a0 = *(const float4*)&As[kk][ty * 8];
            float4 a1 = *(const float4*)&As[kk][ty * 8 + 4];
            float4 b0 = *(const float4*)&Bs[kk][tx * 8];
            float4 b1 = *(const float4*)&Bs[kk][tx * 8 + 4];
            float ar[8] = {a0.x, a0.y, a0.z, a0.w, a1.x, a1.y, a1.z, a1.w};
            float br[8] = {b0.x, b0.y, b0.z, b0.w, b1.x, b1.y, b1.z, b1.w};
#pragma unroll
            for (int i = 0; i < 8; i++)
#pragma unroll
                for (int j = 0; j < 8; j++) acc[i][j] += ar[i] * br[j];
        }
        __syncthreads();
    }

#pragma unroll
    for (int i = 0; i < 8; i++) {
        const int m = m0 + ty * 8 + i;
#pragma unroll
        for (int j = 0; j < 8; j += 4) {
            const int n = n0 + tx * 8 + j;
            float4 bb = *(const float4*)&bo[n];
            float4 v = make_float4(acc[i][j] + bb.x, acc[i][j+1] + bb.y,
                                   acc[i][j+2] + bb.z, acc[i][j+3] + bb.w);
            *(float4*)&Out[(size_t)m * EMB + n] = v;
        }
    }
}

// ---------------------------------------------------------------------------
// Attention v2 (inverted causal mask: attend only strictly-future keys).
// 2 threads per query row (lane pair): each owns 32 of the 64 dims of q and
// the output accumulator (~90 regs vs ~140). Partial QK dots are combined
// with one shfl_xor per key; softmax state is replicated in both lanes, so
// numerics are identical to the proven R1 version (incl. the degenerate
// all-masked last row -> uniform 1/S).
// ---------------------------------------------------------------------------
#define BQ2 128   // queries per block
#define TPB 256   // threads per block (2 per query)
#define BKV 64

__global__ __launch_bounds__(TPB) void attn_kernel()
{
    const int bh = blockIdx.y;              // b*16 + h
    const int b  = bh >> 4;
    const int h  = bh & 15;
    const int q0 = blockIdx.x * BQ2;
    const int t  = threadIdx.x;
    const int qi   = t >> 1;                // query within block
    const int dhalf = (t & 1) * 32;         // dim offset: 0 or 32
    const int qrow = q0 + qi;

    const float* Qb = g_q + (size_t)bh * S_LEN * HDIM;
    const float* Kb = g_k + (size_t)bh * S_LEN * HDIM;
    const float* Vb = g_v + (size_t)bh * S_LEN * HDIM;

    __shared__ float Ks[BKV * HDIM];
    __shared__ float Vs[BKV * HDIM];

    // 32 dims of q in 8 float4
    float4 q4[8];
    const float4* qp = (const float4*)(Qb + (size_t)qrow * HDIM + dhalf);
#pragma unroll
    for (int i = 0; i < 8; i++) q4[i] = qp[i];

    float4 acc[8];
#pragma unroll
    for (int i = 0; i < 8; i++) acc[i] = make_float4(0.f, 0.f, 0.f, 0.f);

    float mrun = -1e30f;
    float lrun = 0.f;
    const float sc_qk = 0.125f;             // 1/sqrt(64)

    const int ntiles = S_LEN / BKV;         // 32
    // Valid keys are k > q >= q0, all in tiles >= q0/BKV. Exception: the block
    // containing row S-1 must see ALL keys so the all-masked row reproduces
    // the reference's uniform softmax exactly.
    const int tstart = (blockIdx.x == gridDim.x - 1) ? 0 : (q0 / BKV);

    for (int kt = tstart; kt < ntiles; kt++) {
        __syncthreads();
        // cooperative K/V tile load (coalesced float4): 1024 float4 x2 / 256 thr
        for (int i = t * 4; i < BKV * HDIM; i += TPB * 4) {
            *(float4*)(Ks + i) = *(const float4*)(Kb + (size_t)kt * BKV * HDIM + i);
            *(float4*)(Vs + i) = *(const float4*)(Vb + (size_t)kt * BKV * HDIM + i);
        }
        __syncthreads();

#pragma unroll 1
        for (int jc = 0; jc < BKV; jc += 8) {
            float sc[8];
#pragma unroll
            for (int jj = 0; jj < 8; jj++) {
                const float4* kp = (const float4*)(Ks + (jc + jj) * HDIM + dhalf);
                float part = 0.f;
#pragma unroll
                for (int i = 0; i < 8; i++) {
                    float4 kv = kp[i];
                    part += q4[i].x * kv.x + q4[i].y * kv.y
                          + q4[i].z * kv.z + q4[i].w * kv.w;
                }
                const float sum = part + __shfl_xor_sync(0xFFFFFFFFu, part, 1);
                const int kg = kt * BKV + jc + jj;
                sc[jj] = (kg > qrow) ? sum * sc_qk : -1e9f;
            }
            float cmax = sc[0];
#pragma unroll
            for (int jj = 1; jj < 8; jj++) cmax = fmaxf(cmax, sc[jj]);
            const float mnew = fmaxf(mrun, cmax);
            const float corr = __expf(mrun - mnew);
            lrun *= corr;
#pragma unroll
            for (int i = 0; i < 8; i++) {
                acc[i].x *= corr; acc[i].y *= corr;
                acc[i].z *= corr; acc[i].w *= corr;
            }
#pragma unroll
            for (int jj = 0; jj < 8; jj++) {
                const float p = __expf(sc[jj] - mnew);
                lrun += p;
                const float4* vp = (const float4*)(Vs + (jc + jj) * HDIM + dhalf);
#pragma unroll
                for (int i = 0; i < 8; i++) {
                    float4 vv = vp[i];
                    acc[i].x += p * vv.x; acc[i].y += p * vv.y;
                    acc[i].z += p * vv.z; acc[i].w += p * vv.w;
                }
            }
            mrun = mnew;
        }
    }

    const float inv = 1.f / lrun;
    float* op = g_att + ((size_t)(b * S_LEN + qrow)) * EMB + h * HDIM + dhalf;
#pragma unroll
    for (int i = 0; i < 8; i++) {
        float4 v = make_float4(acc[i].x * inv, acc[i].y * inv,
                               acc[i].z * inv, acc[i].w * inv);
        ((float4*)op)[i] = v;
    }
}

// ---------------------------------------------------------------------------
extern "C" void kernel_launch(void* const* d_in, const int* in_sizes, int n_in,
                              void* d_out, int out_size)
{
    const float* x  = (const float*)d_in[0];
    const float* wq = (const float*)d_in[1];
    const float* wk = (const float*)d_in[2];
    const float* wv = (const float*)d_in[3];
    const float* wo = (const float*)d_in[4];
    const float* bo = (const float*)d_in[5];
    float* out = (float*)d_out;

    // 1) QKV projections -> g_q/g_k/g_v in [b,h,s,d]
    {
        dim3 grid(EMB / BN, MROWS / BM, 3);
        qkv_gemm<<<grid, 256>>>(x, wq, wk, wv);
    }
    // 2) Attention -> g_att in [b,s,e]
    {
        dim3 grid(S_LEN / BQ2, BATCH * NHEAD);
        attn_kernel<<<grid, TPB>>>();
    }
    // 3) Output projection + bias -> d_out
    {
        dim3 grid(EMB / BN, MROWS / BM);
        outproj_gemm<<<grid, 256>>>(wo, bo, out);
    }
}

// round 13
// speedup vs baseline: 1.3597x; 1.3597x over previous
#include <cuda_runtime.h>

// Problem constants
#define BATCH   2
#define S_LEN   2048
#define EMB     1024
#define NHEAD   16
#define HDIM    64
#define MROWS   (BATCH * S_LEN)          // 4096

// Scratch (allocation-free rule: static __device__ arrays)
__device__ float g_q[BATCH * NHEAD * S_LEN * HDIM];   // [b,h,s,d]
__device__ float g_k[BATCH * NHEAD * S_LEN * HDIM];
__device__ float g_v[BATCH * NHEAD * S_LEN * HDIM];
__device__ float g_att[MROWS * EMB];                  // [b,s,e] e = h*64+d

// ---------------------------------------------------------------------------
// SGEMM (FFMA): C = A @ B^T. 128x128 tile, BK=8, 256 threads, 8x8/thread,
// register prefetch. EXACT R10 kernels (passed, 706us / ~240us).
// TOOLCHAIN NOTE: all tensor-core paths (mma.sync asm, ldmatrix, wmma) trip
// an identical 128MiB local-arena violation on this bench regardless of
// register budget (R5-R9, R11-R12). FFMA-only is the viable lane.
// ---------------------------------------------------------------------------
#define BM 128
#define BN 128
#define BKK 8

__global__ __launch_bounds__(256) void qkv_gemm(
    const float* __restrict__ X,
    const float* __restrict__ Wq,
    const float* __restrict__ Wk,
    const float* __restrict__ Wv)
{
    const int K = EMB;
    const float* W   = (blockIdx.z == 0) ? Wq : (blockIdx.z == 1) ? Wk : Wv;
    float*       Dst = (blockIdx.z == 0) ? g_q : (blockIdx.z == 1) ? g_k : g_v;

    __shared__ float As[BKK][BM];
    __shared__ float Bs[BKK][BN];

    const int tid = threadIdx.x;
    const int m0  = blockIdx.y * BM;
    const int n0  = blockIdx.x * BN;

    const int lrow = tid >> 1;          // 0..127
    const int lcol = (tid & 1) * 4;     // 0 or 4

    const float* Aptr = X + (size_t)(m0 + lrow) * K + lcol;
    const float* Bptr = W + (size_t)(n0 + lrow) * K + lcol;

    float acc[8][8];
#pragma unroll
    for (int i = 0; i < 8; i++)
#pragma unroll
        for (int j = 0; j < 8; j++) acc[i][j] = 0.f;

    const int ty = tid >> 4;   // 0..15
    const int tx = tid & 15;   // 0..15

    float4 a_cur = *(const float4*)(Aptr);
    float4 b_cur = *(const float4*)(Bptr);

    for (int k0 = 0; k0 < K; k0 += BKK) {
        As[lcol + 0][lrow] = a_cur.x; As[lcol + 1][lrow] = a_cur.y;
        As[lcol + 2][lrow] = a_cur.z; As[lcol + 3][lrow] = a_cur.w;
        Bs[lcol + 0][lrow] = b_cur.x; Bs[lcol + 1][lrow] = b_cur.y;
        Bs[lcol + 2][lrow] = b_cur.z; Bs[lcol + 3][lrow] = b_cur.w;
        __syncthreads();

        if (k0 + BKK < K) {
            a_cur = *(const float4*)(Aptr + k0 + BKK);
            b_cur = *(const float4*)(Bptr + k0 + BKK);
        }

#pragma unroll
        for (int kk = 0; kk < BKK; kk++) {
            float4 a0 = *(const float4*)&As[kk][ty * 8];
            float4 a1 = *(const float4*)&As[kk][ty * 8 + 4];
            float4 b0 = *(const float4*)&Bs[kk][tx * 8];
            float4 b1 = *(const float4*)&Bs[kk][tx * 8 + 4];
            float ar[8] = {a0.x, a0.y, a0.z, a0.w, a1.x, a1.y, a1.z, a1.w};
            float br[8] = {b0.x, b0.y, b0.z, b0.w, b1.x, b1.y, b1.z, b1.w};
#pragma unroll
            for (int i = 0; i < 8; i++)
#pragma unroll
                for (int j = 0; j < 8; j++) acc[i][j] += ar[i] * br[j];
        }
        __syncthreads();
    }

#pragma unroll
    for (int i = 0; i < 8; i++) {
        const int m = m0 + ty * 8 + i;
        const int b = m >> 11;          // /2048
        const int s = m & 2047;
#pragma unroll
        for (int j = 0; j < 8; j += 4) {
            const int n = n0 + tx * 8 + j;
            const int h = n >> 6;
            const int d = n & 63;
            float4 v = make_float4(acc[i][j], acc[i][j+1], acc[i][j+2], acc[i][j+3]);
            *(float4*)&Dst[((size_t)(b * NHEAD + h) * S_LEN + s) * HDIM + d] = v;
        }
    }
}

__global__ __launch_bounds__(256) void outproj_gemm(
    const float* __restrict__ Wo,
    const float* __restrict__ bo,
    float* __restrict__ Out)
{
    const int K = EMB;
    const float* A = g_att;

    __shared__ float As[BKK][BM];
    __shared__ float Bs[BKK][BN];

    const int tid = threadIdx.x;
    const int m0  = blockIdx.y * BM;
    const int n0  = blockIdx.x * BN;

    const int lrow = tid >> 1;
    const int lcol = (tid & 1) * 4;

    const float* Aptr = A  + (size_t)(m0 + lrow) * K + lcol;
    const float* Bptr = Wo + (size_t)(n0 + lrow) * K + lcol;

    float acc[8][8];
#pragma unroll
    for (int i = 0; i < 8; i++)
#pragma unroll
        for (int j = 0; j < 8; j++) acc[i][j] = 0.f;

    const int ty = tid >> 4;
    const int tx = tid & 15;

    float4 a_cur = *(const float4*)(Aptr);
    float4 b_cur = *(const float4*)(Bptr);

    for (int k0 = 0; k0 < K; k0 += BKK) {
        As[lcol + 0][lrow] = a_cur.x; As[lcol + 1][lrow] = a_cur.y;
        As[lcol + 2][lrow] = a_cur.z; As[lcol + 3][lrow] = a_cur.w;
        Bs[lcol + 0][lrow] = b_cur.x; Bs[lcol + 1][lrow] = b_cur.y;
        Bs[lcol + 2][lrow] = b_cur.z; Bs[lcol + 3][lrow] = b_cur.w;
        __syncthreads();

        if (k0 + BKK < K) {
            a_cur = *(const float4*)(Aptr + k0 + BKK);
            b_cur = *(const float4*)(Bptr + k0 + BKK);
        }

#pragma unroll
        for (int kk = 0; kk < BKK; kk++) {
            float4 a0 = *(const float4*)&As[kk][ty * 8];
            float4 a1 = *(const float4*)&As[kk][ty * 8 + 4];
            float4 b0 = *(const float4*)&Bs[kk][tx * 8];
            float4 b1 = *(const float4*)&Bs[kk][tx * 8 + 4];
            float ar[8] = {a0.x, a0.y, a0.z, a0.w, a1.x, a1.y, a1.z, a1.w};
            float br[8] = {b0.x, b0.y, b0.z, b0.w, b1.x, b1.y, b1.z, b1.w};
#pragma unroll
            for (int i = 0; i < 8; i++)
#pragma unroll
                for (int j = 0; j < 8; j++) acc[i][j] += ar[i] * br[j];
        }
        __syncthreads();
    }

#pragma unroll
    for (int i = 0; i < 8; i++) {
        const int m = m0 + ty * 8 + i;
#pragma unroll
        for (int j = 0; j < 8; j += 4) {
            const int n = n0 + tx * 8 + j;
            float4 bb = *(const float4*)&bo[n];
            float4 v = make_float4(acc[i][j] + bb.x, acc[i][j+1] + bb.y,
                                   acc[i][j+2] + bb.z, acc[i][j+3] + bb.w);
            *(float4*)&Out[(size_t)m * EMB + n] = v;
        }
    }
}

// ---------------------------------------------------------------------------
// Attention v3 (inverted causal mask: attend only strictly-future keys).
// Same math as the proven R1 kernel (1 thread/query, chunk-8 online softmax
// carrying -1e9; last q-block sees ALL keys so the fully-masked final row
// reproduces the reference's uniform softmax). NEW: double-buffered K/V
// tiles (BKV=32, 2 buffers, one __syncthreads per tile) — issue-slot
// accounting showed R1 ran 7x above its issue-bound because each tile's
// ~600-cycle gmem load phase was fully serialized against compute.
// ---------------------------------------------------------------------------
#define BQ  128
#define BKV 32

__global__ __launch_bounds__(BQ) void attn_kernel()
{
    const int bh = blockIdx.y;              // b*16 + h
    const int b  = bh >> 4;
    const int h  = bh & 15;
    const int q0 = blockIdx.x * BQ;
    const int t  = threadIdx.x;
    const int qrow = q0 + t;

    const float* Qb = g_q + (size_t)bh * S_LEN * HDIM;
    const float* Kb = g_k + (size_t)bh * S_LEN * HDIM;
    const float* Vb = g_v + (size_t)bh * S_LEN * HDIM;

    __shared__ float Ks[2][BKV * HDIM];     // 2 x 8KB
    __shared__ float Vs[2][BKV * HDIM];     // 2 x 8KB

    float4 q4[16];
    const float4* qp = (const float4*)(Qb + (size_t)qrow * HDIM);
#pragma unroll
    for (int i = 0; i < 16; i++) q4[i] = qp[i];

    float4 acc[16];
#pragma unroll
    for (int i = 0; i < 16; i++) acc[i] = make_float4(0.f, 0.f, 0.f, 0.f);

    float mrun = -1e30f;
    float lrun = 0.f;
    const float sc_qk = 0.125f;             // 1/sqrt(64)

    const int ntiles = S_LEN / BKV;         // 64
    // Valid keys are k > q >= q0. Exception: the block containing row S-1
    // must see ALL keys (fully-masked row -> uniform 1/S like the reference).
    const int tstart = (blockIdx.x == gridDim.x - 1) ? 0 : (q0 / BKV);

    // Prologue: load tile tstart into buffer 0.
    {
        const float* kp = Kb + (size_t)tstart * BKV * HDIM;
        const float* vp = Vb + (size_t)tstart * BKV * HDIM;
        for (int i = t * 4; i < BKV * HDIM; i += BQ * 4) {
            *(float4*)(&Ks[0][i]) = *(const float4*)(kp + i);
            *(float4*)(&Vs[0][i]) = *(const float4*)(vp + i);
        }
    }
    __syncthreads();

    for (int kt = tstart; kt < ntiles; kt++) {
        const int buf = (kt - tstart) & 1;

        // Prefetch tile kt+1 into the other buffer (overlaps with compute).
        // Hazard-free: buf^1's readers finished at the sync ending iter kt-1.
        if (kt + 1 < ntiles) {
            const float* kp = Kb + (size_t)(kt + 1) * BKV * HDIM;
            const float* vp = Vb + (size_t)(kt + 1) * BKV * HDIM;
            for (int i = t * 4; i < BKV * HDIM; i += BQ * 4) {
                *(float4*)(&Ks[buf ^ 1][i]) = *(const float4*)(kp + i);
                *(float4*)(&Vs[buf ^ 1][i]) = *(const float4*)(vp + i);
            }
        }

#pragma unroll 1
        for (int jc = 0; jc < BKV; jc += 8) {
            float sc[8];
#pragma unroll
            for (int jj = 0; jj < 8; jj++) {
                const float4* kp = (const float4*)(&Ks[buf][(jc + jj) * HDIM]);
                float sum = 0.f;
#pragma unroll
                for (int i = 0; i < 16; i++) {
                    float4 kv = kp[i];
                    sum += q4[i].x * kv.x + q4[i].y * kv.y
                         + q4[i].z * kv.z + q4[i].w * kv.w;
                }
                const int kg = kt * BKV + jc + jj;
                sc[jj] = (kg > qrow) ? sum * sc_qk : -1e9f;
            }
            float cmax = sc[0];
#pragma unroll
            for (int jj = 1; jj < 8; jj++) cmax = fmaxf(cmax, sc[jj]);
            const float mnew = fmaxf(mrun, cmax);
            const float corr = __expf(mrun - mnew);
            lrun *= corr;
#pragma unroll
            for (int i = 0; i < 16; i++) {
                acc[i].x *= corr; acc[i].y *= corr;
                acc[i].z *= corr; acc[i].w *= corr;
            }
#pragma unroll
            for (int jj = 0; jj < 8; jj++) {
                const float p = __expf(sc[jj] - mnew);
                lrun += p;
                const float4* vp = (const float4*)(&Vs[buf][(jc + jj) * HDIM]);
#pragma unroll
                for (int i = 0; i < 16; i++) {
                    float4 vv = vp[i];
                    acc[i].x += p * vv.x; acc[i].y += p * vv.y;
                    acc[i].z += p * vv.z; acc[i].w += p * vv.w;
                }
            }
            mrun = mnew;
        }
        __syncthreads();
    }

    const float inv = 1.f / lrun;
    float* op = g_att + ((size_t)(b * S_LEN + qrow)) * EMB + h * HDIM;
#pragma unroll
    for (int i = 0; i < 16; i++) {
        float4 v = make_float4(acc[i].x * inv, acc[i].y * inv,
                               acc[i].z * inv, acc[i].w * inv);
        ((float4*)op)[i] = v;
    }
}

// ---------------------------------------------------------------------------
extern "C" void kernel_launch(void* const* d_in, const int* in_sizes, int n_in,
                              void* d_out, int out_size)
{
    const float* x  = (const float*)d_in[0];
    const float* wq = (const float*)d_in[1];
    const float* wk = (const float*)d_in[2];
    const float* wv = (const float*)d_in[3];
    const float* wo = (const float*)d_in[4];
    const float* bo = (const float*)d_in[5];
    float* out = (float*)d_out;

    // 1) QKV projections -> g_q/g_k/g_v in [b,h,s,d]
    {
        dim3 grid(EMB / BN, MROWS / BM, 3);
        qkv_gemm<<<grid, 256>>>(x, wq, wk, wv);
    }
    // 2) Attention -> g_att in [b,s,e]
    {
        dim3 grid(S_LEN / BQ, BATCH * NHEAD);
        attn_kernel<<<grid, BQ>>>();
    }
    // 3) Output projection + bias -> d_out
    {
        dim3 grid(EMB / BN, MROWS / BM);
        outproj_gemm<<<grid, 256>>>(wo, bo, out);
    }
}